// round 3
// baseline (speedup 1.0000x reference)
#include <cuda_runtime.h>

#define N_NODES 150000
#define N_EDGES 2400000
#define F_IN 128
#define HID 32

// ---------------- device scratch (static, no runtime allocation) ----------------
__device__ __align__(16)  int   g_src[N_EDGES];
__device__ __align__(16)  int   g_dst[N_EDGES];
__device__                int   g_deg[N_NODES];
__device__                float g_dinv[N_NODES];
__device__ __align__(128) float g_A[(size_t)N_NODES * HID];   // tp (gather source)
__device__ __align__(128) float g_B[(size_t)N_NODES * HID];   // acc (scatter target)
__device__                float g_tp3[N_NODES];
__device__                float g_acc3[N_NODES];
__device__                int   g_is64;

// ---------------- prep ----------------
__global__ void k_zero_deg() {
    int i = blockIdx.x * blockDim.x + threadIdx.x;
    if (i < N_NODES) g_deg[i] = 0;
}

// Detect whether edge_index arrived as int64 or int32 (JAX x64-off silently
// downcasts). int64 non-negative values < 2^31 have all-zero high words.
__global__ void k_detect(const unsigned int* __restrict__ w) {
    if (blockIdx.x == 0 && threadIdx.x == 0) {
        int is64 = 1;
        #pragma unroll 1
        for (int i = 0; i < 256; i++) {
            if (w[2 * i + 1] != 0u) { is64 = 0; break; }
        }
        g_is64 = is64;
    }
}

__global__ void k_edges(const void* __restrict__ ei) {
    int e = blockIdx.x * blockDim.x + threadIdx.x;
    if (e >= N_EDGES) return;
    int s, d;
    if (g_is64) {
        const long long* p = (const long long*)ei;
        s = (int)p[e];
        d = (int)p[N_EDGES + e];
    } else {
        const int* p = (const int*)ei;
        s = p[e];
        d = p[N_EDGES + e];
    }
    g_src[e] = s;
    g_dst[e] = d;
    atomicAdd(&g_deg[d], 1);
}

__global__ void k_dinv() {
    int i = blockIdx.x * blockDim.x + threadIdx.x;
    if (i < N_NODES) g_dinv[i] = rsqrtf((float)(g_deg[i] + 1));  // +1 self loop
}

// ---------------- GEMM1: tp = dinv * (x @ W1); acc init = tp ----------------
// warp handles 4 rows, lane = output col. W1 staged in shared (16KB),
// x rows staged per-warp in shared (16KB).
__global__ void k_gemm1(const float* __restrict__ x, const float* __restrict__ W1) {
    __shared__ float sW[F_IN * HID];        // 16KB
    __shared__ float sx[8][4][F_IN];        // 8 warps * 4 rows * 128 = 16KB
    for (int i = threadIdx.x; i < F_IN * HID; i += blockDim.x) sW[i] = W1[i];
    __syncthreads();

    int lane = threadIdx.x & 31;
    int warp = threadIdx.x >> 5;
    int nWarps = (gridDim.x * blockDim.x) >> 5;
    int gw = (blockIdx.x * blockDim.x + threadIdx.x) >> 5;
    const int NT = N_NODES / 4;  // 37500 tiles, exact

    for (int t = gw; t < NT; t += nWarps) {
        int base = t * 4;
        // stage 4 contiguous rows = 512 floats = 128 float4 (4 per lane)
        const float4* xs = (const float4*)(x + (size_t)base * F_IN);
        float4* s4 = (float4*)&sx[warp][0][0];
        #pragma unroll
        for (int i = 0; i < 4; i++) s4[lane + 32 * i] = xs[lane + 32 * i];
        __syncwarp();

        float a0 = 0.f, a1 = 0.f, a2 = 0.f, a3 = 0.f;
        #pragma unroll 8
        for (int k = 0; k < F_IN; k++) {
            float wv = sW[k * HID + lane];
            a0 = fmaf(sx[warp][0][k], wv, a0);
            a1 = fmaf(sx[warp][1][k], wv, a1);
            a2 = fmaf(sx[warp][2][k], wv, a2);
            a3 = fmaf(sx[warp][3][k], wv, a3);
        }
        float d0 = g_dinv[base + 0], d1 = g_dinv[base + 1];
        float d2 = g_dinv[base + 2], d3 = g_dinv[base + 3];
        float v;
        v = d0 * a0; g_A[(size_t)(base + 0) * HID + lane] = v; g_B[(size_t)(base + 0) * HID + lane] = v;
        v = d1 * a1; g_A[(size_t)(base + 1) * HID + lane] = v; g_B[(size_t)(base + 1) * HID + lane] = v;
        v = d2 * a2; g_A[(size_t)(base + 2) * HID + lane] = v; g_B[(size_t)(base + 2) * HID + lane] = v;
        v = d3 * a3; g_A[(size_t)(base + 3) * HID + lane] = v; g_B[(size_t)(base + 3) * HID + lane] = v;
        __syncwarp();
    }
}

// ---------------- edge scatter, 32-wide features ----------------
// B[dst] += A[src]; one thread per (edge, float4 chunk). red.v4 => 8 L2
// reduce-ops per edge. 8 consecutive threads share an edge -> gather is a
// coalesced 128B line.
__global__ void k_scatter32() {
    int idx = blockIdx.x * blockDim.x + threadIdx.x;
    if (idx >= N_EDGES * 8) return;
    int e = idx >> 3;
    int c = idx & 7;
    int s = g_src[e];
    int d = g_dst[e];
    float4 v = __ldg((const float4*)(g_A + (size_t)s * HID) + c);
    float4* p = (float4*)(g_B + (size_t)d * HID) + c;
    asm volatile("red.global.add.v4.f32 [%0], {%1,%2,%3,%4};"
                 :: "l"(p), "f"(v.x), "f"(v.y), "f"(v.z), "f"(v.w)
                 : "memory");
}

// ---------------- GEMM2 (fused: relu(dinv*acc1 + b1) -> @W2 -> prescale) ----------------
__global__ void k_gemm2(const float* __restrict__ W2, const float* __restrict__ b1) {
    __shared__ float sW[HID * HID];     // 4KB
    __shared__ float sb[HID];
    __shared__ float sh[8][8][HID];     // 8KB
    for (int i = threadIdx.x; i < HID * HID; i += blockDim.x) sW[i] = W2[i];
    if (threadIdx.x < HID) sb[threadIdx.x] = b1[threadIdx.x];
    __syncthreads();

    int lane = threadIdx.x & 31;
    int warp = threadIdx.x >> 5;
    int nWarps = (gridDim.x * blockDim.x) >> 5;
    int gw = (blockIdx.x * blockDim.x + threadIdx.x) >> 5;
    const int NT = N_NODES / 8;  // 18750, exact

    for (int t = gw; t < NT; t += nWarps) {
        int base = t * 8;
        #pragma unroll
        for (int r = 0; r < 8; r++) {
            int row = base + r;
            float hv = fmaf(g_dinv[row], g_B[(size_t)row * HID + lane], sb[lane]);
            sh[warp][r][lane] = fmaxf(hv, 0.f);
        }
        __syncwarp();
        #pragma unroll
        for (int r = 0; r < 8; r++) {
            float acc = 0.f;
            #pragma unroll
            for (int k = 0; k < HID; k++)
                acc = fmaf(sh[warp][r][k], sW[k * HID + lane], acc);
            int row = base + r;
            float v = g_dinv[row] * acc;
            g_A[(size_t)row * HID + lane] = v;   // tp2
            g_B[(size_t)row * HID + lane] = v;   // acc2 init (self loop)
        }
        __syncwarp();
    }
}

// ---------------- GEMM3 (fused: relu(dinv*acc2 + b2) -> @W3 -> prescale) ----------------
__global__ void k_gemm3(const float* __restrict__ W3, const float* __restrict__ b2) {
    __shared__ float sW[HID], sb[HID];
    if (threadIdx.x < HID) { sW[threadIdx.x] = W3[threadIdx.x]; sb[threadIdx.x] = b2[threadIdx.x]; }
    __syncthreads();
    int i = blockIdx.x * blockDim.x + threadIdx.x;
    if (i >= N_NODES) return;
    float di = g_dinv[i];
    float acc = 0.f;
    const float4* row = (const float4*)(g_B + (size_t)i * HID);
    #pragma unroll
    for (int c = 0; c < 8; c++) {
        float4 v = row[c];
        acc = fmaf(fmaxf(fmaf(di, v.x, sb[4 * c + 0]), 0.f), sW[4 * c + 0], acc);
        acc = fmaf(fmaxf(fmaf(di, v.y, sb[4 * c + 1]), 0.f), sW[4 * c + 1], acc);
        acc = fmaf(fmaxf(fmaf(di, v.z, sb[4 * c + 2]), 0.f), sW[4 * c + 2], acc);
        acc = fmaf(fmaxf(fmaf(di, v.w, sb[4 * c + 3]), 0.f), sW[4 * c + 3], acc);
    }
    float v = di * acc;
    g_tp3[i] = v;
    g_acc3[i] = v;
}

__global__ void k_scatter1() {
    int e = blockIdx.x * blockDim.x + threadIdx.x;
    if (e < N_EDGES)
        atomicAdd(&g_acc3[g_dst[e]], g_tp3[g_src[e]]);   // result unused -> REDG
}

__global__ void k_final(float* __restrict__ out, const float* __restrict__ b3) {
    int i = blockIdx.x * blockDim.x + threadIdx.x;
    if (i < N_NODES) {
        float z = fmaf(g_dinv[i], g_acc3[i], b3[0]);
        out[i] = 1.f / (1.f + expf(-z));
    }
}

// ---------------- launch ----------------
extern "C" void kernel_launch(void* const* d_in, const int* in_sizes, int n_in,
                              void* d_out, int out_size) {
    const float* x  = (const float*)d_in[0];
    const void*  ei = d_in[1];
    const float* W1 = (const float*)d_in[2];
    const float* b1 = (const float*)d_in[3];
    const float* W2 = (const float*)d_in[4];
    const float* b2 = (const float*)d_in[5];
    const float* W3 = (const float*)d_in[6];
    const float* b3 = (const float*)d_in[7];
    float* out = (float*)d_out;

    const int T = 256;
    const int gN = (N_NODES + T - 1) / T;
    const int gE = (N_EDGES + T - 1) / T;
    const int gS = (N_EDGES * 8 + T - 1) / T;

    k_zero_deg<<<gN, T>>>();
    k_detect<<<1, 32>>>((const unsigned int*)ei);
    k_edges<<<gE, T>>>(ei);
    k_dinv<<<gN, T>>>();

    // layer 1
    k_gemm1<<<1184, T>>>(x, W1);
    k_scatter32<<<gS, T>>>();
    // layer 2 (finalize-1 fused into gemm2)
    k_gemm2<<<1184, T>>>(W2, b1);
    k_scatter32<<<gS, T>>>();
    // layer 3 (finalize-2 fused into gemm3)
    k_gemm3<<<gN, T>>>(W3, b2);
    k_scatter1<<<gE, T>>>();
    k_final<<<gN, T>>>(out, b3);
}

// round 4
// speedup vs baseline: 1.0529x; 1.0529x over previous
#include <cuda_runtime.h>

#define N_NODES 150000
#define N_EDGES 2400000
#define F_IN 128
#define HID 32
#define SCAN_B 1024
#define NB1 ((N_NODES + SCAN_B - 1) / SCAN_B)   // 147

// ---------------- device scratch (static, no runtime allocation) ----------------
__device__ __align__(16)  int   g_src[N_EDGES];
__device__ __align__(16)  int   g_dst[N_EDGES];
__device__ __align__(16)  int   g_csr[N_EDGES];     // src ids grouped by dst
__device__                int   g_deg[N_NODES];
__device__                int   g_excl[N_NODES];    // intra-block exclusive scan
__device__                int   g_start[N_NODES];
__device__                int   g_cursor[N_NODES];
__device__                int   g_bsum[NB1];
__device__                float g_dinv[N_NODES];
__device__ __align__(128) float g_A[(size_t)N_NODES * HID];   // tp (gather source)
__device__ __align__(128) float g_B[(size_t)N_NODES * HID];   // aggregated
__device__                float g_tp3[N_NODES];
__device__                int   g_is64;

// ---------------- prep ----------------
__global__ void k_zero_deg() {
    int i = blockIdx.x * blockDim.x + threadIdx.x;
    if (i < N_NODES) g_deg[i] = 0;
}

// Parallel dtype sniff: int64 non-negative ids < 2^31 have all-zero high words.
// If data were int32, the sampled "high words" are random node ids — all-zero
// across 256 samples is impossible in practice.
__global__ void k_detect(const unsigned int* __restrict__ w) {
    unsigned hv = w[2 * threadIdx.x + 1];
    int any = __syncthreads_or(hv != 0u);
    if (threadIdx.x == 0) g_is64 = any ? 0 : 1;
}

__global__ void k_edges(const void* __restrict__ ei) {
    int e = blockIdx.x * blockDim.x + threadIdx.x;
    if (e >= N_EDGES) return;
    int s, d;
    if (g_is64) {
        const long long* p = (const long long*)ei;
        s = (int)p[e];
        d = (int)p[N_EDGES + e];
    } else {
        const int* p = (const int*)ei;
        s = p[e];
        d = p[N_EDGES + e];
    }
    g_src[e] = s;
    g_dst[e] = d;
    atomicAdd(&g_deg[d], 1);
}

// ---- exclusive scan of g_deg -> g_start (3 kernels) ----
__global__ void k_scan1() {
    __shared__ int sh[SCAN_B];
    int i = blockIdx.x * SCAN_B + threadIdx.x;
    int v = (i < N_NODES) ? g_deg[i] : 0;
    int sum = v;
    sh[threadIdx.x] = sum;
    __syncthreads();
    for (int off = 1; off < SCAN_B; off <<= 1) {
        int t = (threadIdx.x >= off) ? sh[threadIdx.x - off] : 0;
        __syncthreads();
        sum += t;
        sh[threadIdx.x] = sum;
        __syncthreads();
    }
    if (i < N_NODES) g_excl[i] = sum - v;
    if (threadIdx.x == SCAN_B - 1) g_bsum[blockIdx.x] = sum;
}

__global__ void k_scan2() {   // one block, 256 threads, NB1=147 partials
    __shared__ int wsum[8];
    int tid = threadIdx.x, lane = tid & 31, w = tid >> 5;
    int v = (tid < NB1) ? g_bsum[tid] : 0;
    int s = v;
    #pragma unroll
    for (int off = 1; off < 32; off <<= 1) {
        int t = __shfl_up_sync(0xffffffffu, s, off);
        if (lane >= off) s += t;
    }
    if (lane == 31) wsum[w] = s;
    __syncthreads();
    if (w == 0) {
        int ws = (lane < 8) ? wsum[lane] : 0;
        #pragma unroll
        for (int off = 1; off < 8; off <<= 1) {
            int t = __shfl_up_sync(0xffffffffu, ws, off);
            if (lane >= off) ws += t;
        }
        if (lane < 8) wsum[lane] = ws;
    }
    __syncthreads();
    int base = (w > 0) ? wsum[w - 1] : 0;
    if (tid < NB1) g_bsum[tid] = base + s - v;   // exclusive
}

__global__ void k_scan3() {
    int i = blockIdx.x * blockDim.x + threadIdx.x;
    if (i >= N_NODES) return;
    int start = g_excl[i] + g_bsum[i >> 10];
    g_start[i]  = start;
    g_cursor[i] = start;
    g_dinv[i]   = rsqrtf((float)(g_deg[i] + 1));   // +1 self loop
}

__global__ void k_fill() {
    int e = blockIdx.x * blockDim.x + threadIdx.x;
    if (e >= N_EDGES) return;
    int pos = atomicAdd(&g_cursor[g_dst[e]], 1);
    g_csr[pos] = g_src[e];
}

// ---------------- GEMM1: tp = dinv * (x @ W1) ----------------
__global__ void k_gemm1(const float* __restrict__ x, const float* __restrict__ W1) {
    __shared__ float sW[F_IN * HID];        // 16KB
    __shared__ float sx[8][4][F_IN];        // 16KB
    for (int i = threadIdx.x; i < F_IN * HID; i += blockDim.x) sW[i] = W1[i];
    __syncthreads();

    int lane = threadIdx.x & 31;
    int warp = threadIdx.x >> 5;
    int nWarps = (gridDim.x * blockDim.x) >> 5;
    int gw = (blockIdx.x * blockDim.x + threadIdx.x) >> 5;
    const int NT = N_NODES / 4;

    for (int t = gw; t < NT; t += nWarps) {
        int base = t * 4;
        const float4* xs = (const float4*)(x + (size_t)base * F_IN);
        float4* s4 = (float4*)&sx[warp][0][0];
        #pragma unroll
        for (int i = 0; i < 4; i++) s4[lane + 32 * i] = xs[lane + 32 * i];
        __syncwarp();

        float a0 = 0.f, a1 = 0.f, a2 = 0.f, a3 = 0.f;
        #pragma unroll 8
        for (int k = 0; k < F_IN; k++) {
            float wv = sW[k * HID + lane];
            a0 = fmaf(sx[warp][0][k], wv, a0);
            a1 = fmaf(sx[warp][1][k], wv, a1);
            a2 = fmaf(sx[warp][2][k], wv, a2);
            a3 = fmaf(sx[warp][3][k], wv, a3);
        }
        g_A[(size_t)(base + 0) * HID + lane] = g_dinv[base + 0] * a0;
        g_A[(size_t)(base + 1) * HID + lane] = g_dinv[base + 1] * a1;
        g_A[(size_t)(base + 2) * HID + lane] = g_dinv[base + 2] * a2;
        g_A[(size_t)(base + 3) * HID + lane] = g_dinv[base + 3] * a3;
        __syncwarp();
    }
}

// ---------------- CSR aggregate, 32-wide: B[i] = A[i] + sum_{s in adj(i)} A[s] ----------------
// One warp per node, lane = feature column. Register accumulation, single store.
__global__ void k_agg32() {
    int node = (blockIdx.x * blockDim.x + threadIdx.x) >> 5;   // exact: 150000 warps
    int lane = threadIdx.x & 31;
    int start = g_start[node];
    int n = g_deg[node];

    float acc0 = __ldg(&g_A[(size_t)node * HID + lane]);       // self loop
    float acc1 = 0.f;

    int nchunks = (n + 31) >> 5;
    for (int c = 0; c < nchunks; c++) {
        int j = (c << 5) + lane;
        int s = (j < n) ? __ldg(&g_csr[start + j]) : -1;
        int rem = n - (c << 5);
        #pragma unroll
        for (int t = 0; t < 32; t += 4) {
            if (t >= rem) break;
            int s0 = __shfl_sync(0xffffffffu, s, t + 0);
            int s1 = __shfl_sync(0xffffffffu, s, t + 1);
            int s2 = __shfl_sync(0xffffffffu, s, t + 2);
            int s3 = __shfl_sync(0xffffffffu, s, t + 3);
            float v0 = (t + 0 < rem) ? __ldg(&g_A[(size_t)s0 * HID + lane]) : 0.f;
            float v1 = (t + 1 < rem) ? __ldg(&g_A[(size_t)s1 * HID + lane]) : 0.f;
            float v2 = (t + 2 < rem) ? __ldg(&g_A[(size_t)s2 * HID + lane]) : 0.f;
            float v3 = (t + 3 < rem) ? __ldg(&g_A[(size_t)s3 * HID + lane]) : 0.f;
            acc0 += v0 + v1;
            acc1 += v2 + v3;
        }
    }
    g_B[(size_t)node * HID + lane] = acc0 + acc1;
}

// ---------------- GEMM2 (fused: relu(dinv*B + b1) -> @W2 -> prescale) ----------------
__global__ void k_gemm2(const float* __restrict__ W2, const float* __restrict__ b1) {
    __shared__ float sW[HID * HID];
    __shared__ float sb[HID];
    __shared__ float sh[8][8][HID];
    for (int i = threadIdx.x; i < HID * HID; i += blockDim.x) sW[i] = W2[i];
    if (threadIdx.x < HID) sb[threadIdx.x] = b1[threadIdx.x];
    __syncthreads();

    int lane = threadIdx.x & 31;
    int warp = threadIdx.x >> 5;
    int nWarps = (gridDim.x * blockDim.x) >> 5;
    int gw = (blockIdx.x * blockDim.x + threadIdx.x) >> 5;
    const int NT = N_NODES / 8;

    for (int t = gw; t < NT; t += nWarps) {
        int base = t * 8;
        #pragma unroll
        for (int r = 0; r < 8; r++) {
            int row = base + r;
            float hv = fmaf(g_dinv[row], g_B[(size_t)row * HID + lane], sb[lane]);
            sh[warp][r][lane] = fmaxf(hv, 0.f);
        }
        __syncwarp();
        #pragma unroll
        for (int r = 0; r < 8; r++) {
            float acc = 0.f;
            #pragma unroll
            for (int k = 0; k < HID; k++)
                acc = fmaf(sh[warp][r][k], sW[k * HID + lane], acc);
            int row = base + r;
            g_A[(size_t)row * HID + lane] = g_dinv[row] * acc;
        }
        __syncwarp();
    }
}

// ---------------- GEMM3 (fused: relu(dinv*B + b2) -> @W3 -> prescale) ----------------
__global__ void k_gemm3(const float* __restrict__ W3, const float* __restrict__ b2) {
    __shared__ float sW[HID], sb[HID];
    if (threadIdx.x < HID) { sW[threadIdx.x] = W3[threadIdx.x]; sb[threadIdx.x] = b2[threadIdx.x]; }
    __syncthreads();
    int i = blockIdx.x * blockDim.x + threadIdx.x;
    if (i >= N_NODES) return;
    float di = g_dinv[i];
    float acc = 0.f;
    const float4* row = (const float4*)(g_B + (size_t)i * HID);
    #pragma unroll
    for (int c = 0; c < 8; c++) {
        float4 v = row[c];
        acc = fmaf(fmaxf(fmaf(di, v.x, sb[4 * c + 0]), 0.f), sW[4 * c + 0], acc);
        acc = fmaf(fmaxf(fmaf(di, v.y, sb[4 * c + 1]), 0.f), sW[4 * c + 1], acc);
        acc = fmaf(fmaxf(fmaf(di, v.z, sb[4 * c + 2]), 0.f), sW[4 * c + 2], acc);
        acc = fmaf(fmaxf(fmaf(di, v.w, sb[4 * c + 3]), 0.f), sW[4 * c + 3], acc);
    }
    g_tp3[i] = di * acc;
}

// ---------------- layer-3 CSR aggregate + bias + sigmoid (fused finalize) ----------------
__global__ void k_agg1_final(float* __restrict__ out, const float* __restrict__ b3) {
    int i = blockIdx.x * blockDim.x + threadIdx.x;
    if (i >= N_NODES) return;
    int start = g_start[i];
    int n = g_deg[i];
    float a0 = g_tp3[i], a1 = 0.f, a2 = 0.f, a3 = 0.f;   // self loop in a0
    int j = 0;
    for (; j + 4 <= n; j += 4) {
        int s0 = g_csr[start + j + 0];
        int s1 = g_csr[start + j + 1];
        int s2 = g_csr[start + j + 2];
        int s3 = g_csr[start + j + 3];
        a0 += __ldg(&g_tp3[s0]);
        a1 += __ldg(&g_tp3[s1]);
        a2 += __ldg(&g_tp3[s2]);
        a3 += __ldg(&g_tp3[s3]);
    }
    for (; j < n; j++) a0 += __ldg(&g_tp3[g_csr[start + j]]);
    float z = fmaf(g_dinv[i], (a0 + a1) + (a2 + a3), b3[0]);
    out[i] = 1.f / (1.f + expf(-z));
}

// ---------------- launch ----------------
extern "C" void kernel_launch(void* const* d_in, const int* in_sizes, int n_in,
                              void* d_out, int out_size) {
    const float* x  = (const float*)d_in[0];
    const void*  ei = d_in[1];
    const float* W1 = (const float*)d_in[2];
    const float* b1 = (const float*)d_in[3];
    const float* W2 = (const float*)d_in[4];
    const float* b2 = (const float*)d_in[5];
    const float* W3 = (const float*)d_in[6];
    const float* b3 = (const float*)d_in[7];
    float* out = (float*)d_out;

    const int T = 256;
    const int gN = (N_NODES + T - 1) / T;
    const int gE = (N_EDGES + T - 1) / T;
    const int gW = (N_NODES * 32) / T;       // warp-per-node aggregate: 18750

    // CSR build
    k_zero_deg<<<gN, T>>>();
    k_detect<<<1, 256>>>((const unsigned int*)ei);
    k_edges<<<gE, T>>>(ei);
    k_scan1<<<NB1, SCAN_B>>>();
    k_scan2<<<1, 256>>>();
    k_scan3<<<gN, T>>>();
    k_fill<<<gE, T>>>();

    // layer 1
    k_gemm1<<<1184, T>>>(x, W1);
    k_agg32<<<gW, T>>>();
    // layer 2
    k_gemm2<<<1184, T>>>(W2, b1);
    k_agg32<<<gW, T>>>();
    // layer 3
    k_gemm3<<<gN, T>>>(W3, b2);
    k_agg1_final<<<gN, T>>>(out, b3);
}